// round 11
// baseline (speedup 1.0000x reference)
#include <cuda_runtime.h>
#include <cuda_fp16.h>

#define N_NODES 50000
#define N_EDGES 500000
#define NUMK 4
#define FDIM 64
#define DDIM 32
#define NBE 64
#define NBND 63
#define GP 68

// Scratch (device globals; zero-initialized at module load)
__device__ __align__(128) float g_y[(size_t)N_NODES * 128];  // zeroed by k_gemm after use
__device__ float g_s[N_NODES];
__device__ int g_cin[N_NODES];
__device__ int g_cout[N_NODES];
__device__ __align__(128) __half g_Th[NBE * FDIM];              // fp16 T table
__device__ __align__(128) __half g_fh[(size_t)N_NODES * FDIM];  // fp16 features
__device__ __align__(16) float4 g_loc4[N_NODES];                // padded positions

__device__ __forceinline__ void red_add4(float* p, float x, float y, float z, float w) {
    asm volatile("red.global.add.v4.f32 [%0], {%1,%2,%3,%4};"
                 :: "l"(p), "f"(x), "f"(y), "f"(z), "f"(w));
}
__device__ __forceinline__ void red_add1(float* p, float x) {
    asm volatile("red.global.add.f32 [%0], %1;" :: "l"(p), "f"(x));
}
__device__ __forceinline__ void ffma2(unsigned long long& d,
                                      unsigned long long a, unsigned long long b) {
    asm("fma.rn.f32x2 %0, %1, %2, %0;" : "+l"(d) : "l"(a), "l"(b));
}
__device__ __forceinline__ unsigned long long pack2(float lo, float hi) {
    unsigned long long r;
    asm("mov.b64 %0, {%1, %2};" : "=l"(r) : "f"(lo), "f"(hi));
    return r;
}

// Prep: zero counters/s, fp16 T table, fp16 feat, padded loc4.
// (g_y zeroing moved to k_gemm's consume-and-reset.)
__global__ __launch_bounds__(256) void k_prep(
    const float* __restrict__ emb, const float* __restrict__ gw,
    const float* __restrict__ feat, const float* __restrict__ loc)
{
    int i = blockIdx.x * blockDim.x + threadIdx.x;
    int stride = gridDim.x * blockDim.x;
    for (int j = i; j < N_NODES; j += stride) {
        g_cin[j] = 0; g_cout[j] = 0; g_s[j] = 0.f;
        g_loc4[j] = make_float4(loc[j * 3], loc[j * 3 + 1], loc[j * 3 + 2], 0.f);
    }
    const float2* f2 = reinterpret_cast<const float2*>(feat);
    __half2* h2 = reinterpret_cast<__half2*>(g_fh);
    for (int j = i; j < N_NODES * FDIM / 2; j += stride) {
        float2 v = f2[j];
        h2[j] = __floats2half2_rn(v.x, v.y);
    }
    for (int j = i; j < NBE * FDIM; j += stride) {
        int b = j >> 6, f = j & 63;
        float acc = 0.f;
#pragma unroll
        for (int d = 0; d < DDIM; d++) acc += emb[b * DDIM + d] * gw[f * DDIM + d];
        g_Th[j] = __float2half_rn(acc);
    }
}

__global__ void k_deg(const int* __restrict__ src, const int* __restrict__ dst) {
    int e = blockIdx.x * blockDim.x + threadIdx.x;
    if (e < N_EDGES) {
        atomicAdd(&g_cin[dst[e]], 1);
        atomicAdd(&g_cout[src[e]], 1);
    }
}

// Fused dist + feat. Phase 1: one thread per edge computes buckets/sc into
// shared headers. Phase 2: 8 warps run the divergence-free feat body
// (2 edges per warp per iteration) reading headers via LDS broadcast.
__global__ __launch_bounds__(256) void k_main(
    const float* __restrict__ bnd,
    const int* __restrict__ src, const int* __restrict__ dst,
    const int* __restrict__ inter)
{
    __shared__ float sb[64];
    __shared__ __align__(16) __half sT[NBE * FDIM];   // 8 KB
    __shared__ __align__(16) int4 shA[256];           // {si|di<<16, pk1, pk2, pk3}
    __shared__ __align__(16) int4 shB[256];           // {pk4, b1, sc_bits, 0}

    int t = threadIdx.x;
    if (t < NBND) sb[t] = bnd[t];
    {
        uint2* d = reinterpret_cast<uint2*>(sT);
        const uint2* s = reinterpret_cast<const uint2*>(g_Th);
#pragma unroll
        for (int k = 0; k < 4; k++) d[t + 256 * k] = s[t + 256 * k];
    }
    __syncthreads();

    // ---- phase 1: dist/bucket/sc ----
    int e0 = blockIdx.x * 256 + t;
    if (e0 < N_EDGES) {
        int si = __ldg(&src[e0]);
        int di = __ldg(&dst[e0]);
        float4 sp = __ldg(&g_loc4[si]);

        int others[5];
        others[0] = di;
#pragma unroll
        for (int k = 0; k < NUMK; k++) others[k + 1] = __ldg(&inter[(size_t)e0 * NUMK + k]);

        int pk[5];
#pragma unroll
        for (int s = 0; s < 5; s++) {
            int o = others[s];
            float4 op = __ldg(&g_loc4[o]);
            float dx = sp.x - op.x, dy = sp.y - op.y, dz = sp.z - op.z;
            float dv = sqrtf(dx * dx + dy * dy + dz * dz);
            int pos = 0;
#pragma unroll
            for (int step = 32; step >= 1; step >>= 1)
                if (pos + step <= NBND && sb[pos + step - 1] < dv) pos += step;
            pk[s] = (o << 6) | pos;
        }

        float sc = rsqrtf(fmaxf((float)__ldg(&g_cin[di]), 1.f)) *
                   rsqrtf(fmaxf((float)__ldg(&g_cout[si]), 1.f));
        red_add1(&g_s[di], sc);

        shA[t] = make_int4(si | (di << 16), pk[1], pk[2], pk[3]);
        shB[t] = make_int4(pk[4], pk[0] & 63, __float_as_int(sc), 0);
    }
    __syncthreads();

    // ---- phase 2: feature accumulate (divergence-free, 2 edges/warp/iter) ----
    int lane = t & 31;
    int w = t >> 5;
    int hl = lane & 15;
    int half = lane >> 4;
    int j = hl * 4;

#pragma unroll 4
    for (int i = 0; i < 16; i++) {
        int el = w * 32 + i * 2 + half;
        int e = blockIdx.x * 256 + el;
        if (e >= N_EDGES) continue;

        int4 A = shA[el];
        int4 B = shB[el];
        int si = A.x & 0xffff;
        int di = (A.x >> 16) & 0xffff;
        float sc = __int_as_float(B.z);

        uint2 hv = __ldg(reinterpret_cast<const uint2*>(g_fh + (size_t)si * FDIM + j));
        uint2 tv = *reinterpret_cast<const uint2*>(sT + B.y * FDIM + j);
        __half2 p0 = __hmul2(*reinterpret_cast<__half2*>(&hv.x), *reinterpret_cast<__half2*>(&tv.x));
        __half2 p1 = __hmul2(*reinterpret_cast<__half2*>(&hv.y), *reinterpret_cast<__half2*>(&tv.y));
        float2 f0 = __half22float2(p0), f1 = __half22float2(p1);

        float ax = 0.f, ay = 0.f, az = 0.f, aw = 0.f;
        int pv[4] = {A.y, A.z, A.w, B.x};
#pragma unroll
        for (int k = 0; k < NUMK; k++) {
            int id = pv[k] >> 6, bk = pv[k] & 63;
            uint2 h = __ldg(reinterpret_cast<const uint2*>(g_fh + (size_t)id * FDIM + j));
            uint2 tt = *reinterpret_cast<const uint2*>(sT + bk * FDIM + j);
            __half2 q0 = __hmul2(*reinterpret_cast<__half2*>(&h.x), *reinterpret_cast<__half2*>(&tt.x));
            __half2 q1 = __hmul2(*reinterpret_cast<__half2*>(&h.y), *reinterpret_cast<__half2*>(&tt.y));
            float2 g0 = __half22float2(q0), g1 = __half22float2(q1);
            ax += g0.x; ay += g0.y; az += g1.x; aw += g1.y;
        }
        float f4 = sc * 0.25f;

        float* yrow = g_y + (size_t)di * 128;
        red_add4(yrow + j,      sc * f0.x, sc * f0.y, sc * f1.x, sc * f1.y);
        red_add4(yrow + 64 + j, f4 * ax, f4 * ay, f4 * az, f4 * aw);
    }
}

// out[v][f] = sum_j y[v][j] * W[f][j] + s[v] * b[f]
// Also zeroes g_y after consuming it (replay-safe: y is exclusively owned
// per block, and module-load zero-init covers the first call).
__global__ __launch_bounds__(256) void k_gemm(
    const float* __restrict__ W, const float* __restrict__ bvec,
    float* __restrict__ out)
{
    extern __shared__ float smem[];
    float* sW = smem;
    float* sY = smem + 128 * GP;
    int t = threadIdx.x;
    int vbase = blockIdx.x * 64;

    for (int idx = t; idx < FDIM * 128; idx += 256) {
        int f = idx >> 7, j = idx & 127;
        sW[j * GP + f] = W[idx];
    }
    for (int idx = t; idx < 64 * 128; idx += 256) {
        int v = idx >> 7, j = idx & 127;
        int gv = vbase + v;
        float val = 0.f;
        if (gv < N_NODES) {
            size_t a = (size_t)gv * 128 + j;
            val = g_y[a];
            g_y[a] = 0.f;     // consume-and-reset for next replay
        }
        sY[j * GP + v] = val;
    }
    __syncthreads();

    int f0 = (t & 15) * 4;
    int v0 = (t >> 4) * 4;
    unsigned long long accp[4][2];
#pragma unroll
    for (int a = 0; a < 4; a++) { accp[a][0] = 0ull; accp[a][1] = 0ull; }

#pragma unroll 4
    for (int j = 0; j < 128; j++) {
        float4 wv = *reinterpret_cast<float4*>(&sW[j * GP + f0]);
        float4 yv = *reinterpret_cast<float4*>(&sY[j * GP + v0]);
        unsigned long long wp0 = pack2(wv.x, wv.y);
        unsigned long long wp1 = pack2(wv.z, wv.w);
        float yr[4] = {yv.x, yv.y, yv.z, yv.w};
#pragma unroll
        for (int a = 0; a < 4; a++) {
            unsigned long long yb = pack2(yr[a], yr[a]);
            ffma2(accp[a][0], yb, wp0);
            ffma2(accp[a][1], yb, wp1);
        }
    }

    float4 bb = *reinterpret_cast<const float4*>(bvec + f0);
#pragma unroll
    for (int a = 0; a < 4; a++) {
        int v = vbase + v0 + a;
        if (v < N_NODES) {
            float sv = g_s[v];
            float2 c0 = *reinterpret_cast<float2*>(&accp[a][0]);
            float2 c1 = *reinterpret_cast<float2*>(&accp[a][1]);
            float4 o;
            o.x = c0.x + sv * bb.x;
            o.y = c0.y + sv * bb.y;
            o.z = c1.x + sv * bb.z;
            o.w = c1.y + sv * bb.w;
            *reinterpret_cast<float4*>(out + (size_t)v * FDIM + f0) = o;
        }
    }
}

extern "C" void kernel_launch(void* const* d_in, const int* in_sizes, int n_in,
                              void* d_out, int out_size) {
    const float* feat = (const float*)d_in[0];
    const float* loc  = (const float*)d_in[1];
    const float* bnd  = (const float*)d_in[2];
    const float* emb  = (const float*)d_in[3];
    const float* gw   = (const float*)d_in[4];
    const float* aggw = (const float*)d_in[5];
    const float* aggb = (const float*)d_in[6];
    const int* src   = (const int*)d_in[7];
    const int* dst   = (const int*)d_in[8];
    const int* inter = (const int*)d_in[9];
    float* out = (float*)d_out;

    k_prep<<<512, 256>>>(emb, gw, feat, loc);                       // 1
    k_deg<<<(N_EDGES + 255) / 256, 256>>>(src, dst);                // 2
    k_main<<<(N_EDGES + 255) / 256, 256>>>(bnd, src, dst, inter);   // 3
    size_t smem = 2 * 128 * GP * sizeof(float);
    cudaFuncSetAttribute(k_gemm, cudaFuncAttributeMaxDynamicSharedMemorySize, (int)smem);
    k_gemm<<<(N_NODES + 63) / 64, 256, smem>>>(aggw, aggb, out);    // 4
}

// round 13
// speedup vs baseline: 2.0410x; 2.0410x over previous
#include <cuda_runtime.h>
#include <cuda_fp16.h>

#define N_NODES 50000
#define N_EDGES 500000
#define NUMK 4
#define FDIM 64
#define DDIM 32
#define NBE 64
#define NBND 63
#define GP 68

// Scratch (device globals)
__device__ __align__(128) float g_y[(size_t)N_NODES * 128];
__device__ float g_s[N_NODES];
__device__ int g_cin[N_NODES];
__device__ int g_cout[N_NODES];
__device__ __align__(128) __half g_Th[NBE * FDIM];              // fp16 T table
__device__ __align__(128) __half g_fh[(size_t)N_NODES * FDIM];  // fp16 features
__device__ __align__(16) float4 g_loc4[N_NODES];                // padded positions

__device__ __forceinline__ void red_add4(float* p, float x, float y, float z, float w) {
    asm volatile("red.global.add.v4.f32 [%0], {%1,%2,%3,%4};"
                 :: "l"(p), "f"(x), "f"(y), "f"(z), "f"(w));
}
__device__ __forceinline__ void red_add1(float* p, float x) {
    asm volatile("red.global.add.f32 [%0], %1;" :: "l"(p), "f"(x));
}
__device__ __forceinline__ void ffma2(unsigned long long& d,
                                      unsigned long long a, unsigned long long b) {
    asm("fma.rn.f32x2 %0, %1, %2, %0;" : "+l"(d) : "l"(a), "l"(b));
}
__device__ __forceinline__ unsigned long long pack2(float lo, float hi) {
    unsigned long long r;
    asm("mov.b64 %0, {%1, %2};" : "=l"(r) : "f"(lo), "f"(hi));
    return r;
}

// Prep: zero y (float4, streaming), zero counters/s, fp16 T, fp16 feat, loc4.
__global__ __launch_bounds__(256) void k_prep(
    const float* __restrict__ emb, const float* __restrict__ gw,
    const float* __restrict__ feat, const float* __restrict__ loc)
{
    int i = blockIdx.x * blockDim.x + threadIdx.x;
    int stride = gridDim.x * blockDim.x;
    float4 z = make_float4(0.f, 0.f, 0.f, 0.f);
    float4* y4 = reinterpret_cast<float4*>(g_y);
    for (int j = i; j < N_NODES * 32; j += stride) y4[j] = z;
    for (int j = i; j < N_NODES; j += stride) {
        g_cin[j] = 0; g_cout[j] = 0; g_s[j] = 0.f;
        g_loc4[j] = make_float4(loc[j * 3], loc[j * 3 + 1], loc[j * 3 + 2], 0.f);
    }
    const float2* f2 = reinterpret_cast<const float2*>(feat);
    __half2* h2 = reinterpret_cast<__half2*>(g_fh);
    for (int j = i; j < N_NODES * FDIM / 2; j += stride) {
        float2 v = f2[j];
        h2[j] = __floats2half2_rn(v.x, v.y);
    }
    for (int j = i; j < NBE * FDIM; j += stride) {
        int b = j >> 6, f = j & 63;
        float acc = 0.f;
#pragma unroll
        for (int d = 0; d < DDIM; d++) acc += emb[b * DDIM + d] * gw[f * DDIM + d];
        g_Th[j] = __float2half_rn(acc);
    }
}

__global__ void k_deg(const int* __restrict__ src, const int* __restrict__ dst) {
    int e = blockIdx.x * blockDim.x + threadIdx.x;
    if (e < N_EDGES) {
        atomicAdd(&g_cin[dst[e]], 1);
        atomicAdd(&g_cout[src[e]], 1);
    }
}

// Fused dist + feat (kept from R11). Phase 1: per-thread buckets/sc into
// shared headers. Phase 2: divergence-free feat body, 2 edges/warp/iter.
__global__ __launch_bounds__(256) void k_main(
    const float* __restrict__ bnd,
    const int* __restrict__ src, const int* __restrict__ dst,
    const int* __restrict__ inter)
{
    __shared__ float sb[64];
    __shared__ __align__(16) __half sT[NBE * FDIM];   // 8 KB
    __shared__ __align__(16) int4 shA[256];
    __shared__ __align__(16) int4 shB[256];

    int t = threadIdx.x;
    if (t < NBND) sb[t] = bnd[t];
    {
        uint2* d = reinterpret_cast<uint2*>(sT);
        const uint2* s = reinterpret_cast<const uint2*>(g_Th);
#pragma unroll
        for (int k = 0; k < 4; k++) d[t + 256 * k] = s[t + 256 * k];
    }
    __syncthreads();

    // ---- phase 1: dist/bucket/sc ----
    int e0 = blockIdx.x * 256 + t;
    if (e0 < N_EDGES) {
        int si = __ldg(&src[e0]);
        int di = __ldg(&dst[e0]);
        float4 sp = __ldg(&g_loc4[si]);

        int others[5];
        others[0] = di;
#pragma unroll
        for (int k = 0; k < NUMK; k++) others[k + 1] = __ldg(&inter[(size_t)e0 * NUMK + k]);

        int pk[5];
#pragma unroll
        for (int s = 0; s < 5; s++) {
            int o = others[s];
            float4 op = __ldg(&g_loc4[o]);
            float dx = sp.x - op.x, dy = sp.y - op.y, dz = sp.z - op.z;
            float dv = sqrtf(dx * dx + dy * dy + dz * dz);
            int pos = 0;
#pragma unroll
            for (int step = 32; step >= 1; step >>= 1)
                if (pos + step <= NBND && sb[pos + step - 1] < dv) pos += step;
            pk[s] = (o << 6) | pos;
        }

        float sc = rsqrtf(fmaxf((float)__ldg(&g_cin[di]), 1.f)) *
                   rsqrtf(fmaxf((float)__ldg(&g_cout[si]), 1.f));
        red_add1(&g_s[di], sc);

        shA[t] = make_int4(si | (di << 16), pk[1], pk[2], pk[3]);
        shB[t] = make_int4(pk[4], pk[0] & 63, __float_as_int(sc), 0);
    }
    __syncthreads();

    // ---- phase 2: feature accumulate ----
    int lane = t & 31;
    int w = t >> 5;
    int hl = lane & 15;
    int half = lane >> 4;
    int j = hl * 4;

#pragma unroll 4
    for (int i = 0; i < 16; i++) {
        int el = w * 32 + i * 2 + half;
        int e = blockIdx.x * 256 + el;
        if (e >= N_EDGES) continue;

        int4 A = shA[el];
        int4 B = shB[el];
        int si = A.x & 0xffff;
        int di = (A.x >> 16) & 0xffff;
        float sc = __int_as_float(B.z);

        uint2 hv = __ldg(reinterpret_cast<const uint2*>(g_fh + (size_t)si * FDIM + j));
        uint2 tv = *reinterpret_cast<const uint2*>(sT + B.y * FDIM + j);
        __half2 p0 = __hmul2(*reinterpret_cast<__half2*>(&hv.x), *reinterpret_cast<__half2*>(&tv.x));
        __half2 p1 = __hmul2(*reinterpret_cast<__half2*>(&hv.y), *reinterpret_cast<__half2*>(&tv.y));
        float2 f0 = __half22float2(p0), f1 = __half22float2(p1);

        float ax = 0.f, ay = 0.f, az = 0.f, aw = 0.f;
        int pv[4] = {A.y, A.z, A.w, B.x};
#pragma unroll
        for (int k = 0; k < NUMK; k++) {
            int id = pv[k] >> 6, bk = pv[k] & 63;
            uint2 h = __ldg(reinterpret_cast<const uint2*>(g_fh + (size_t)id * FDIM + j));
            uint2 tt = *reinterpret_cast<const uint2*>(sT + bk * FDIM + j);
            __half2 q0 = __hmul2(*reinterpret_cast<__half2*>(&h.x), *reinterpret_cast<__half2*>(&tt.x));
            __half2 q1 = __hmul2(*reinterpret_cast<__half2*>(&h.y), *reinterpret_cast<__half2*>(&tt.y));
            float2 g0 = __half22float2(q0), g1 = __half22float2(q1);
            ax += g0.x; ay += g0.y; az += g1.x; aw += g1.y;
        }
        float f4 = sc * 0.25f;

        float* yrow = g_y + (size_t)di * 128;
        red_add4(yrow + j,      sc * f0.x, sc * f0.y, sc * f1.x, sc * f1.y);
        red_add4(yrow + 64 + j, f4 * ax, f4 * ay, f4 * az, f4 * aw);
    }
}

// out[v][f] = sum_j y[v][j] * W[f][j] + s[v] * b[f]   (R10 form, no y-store)
__global__ __launch_bounds__(256) void k_gemm(
    const float* __restrict__ W, const float* __restrict__ bvec,
    float* __restrict__ out)
{
    extern __shared__ float smem[];
    float* sW = smem;
    float* sY = smem + 128 * GP;
    int t = threadIdx.x;
    int vbase = blockIdx.x * 64;

    for (int idx = t; idx < FDIM * 128; idx += 256) {
        int f = idx >> 7, j = idx & 127;
        sW[j * GP + f] = W[idx];
    }
    for (int idx = t; idx < 64 * 128; idx += 256) {
        int v = idx >> 7, j = idx & 127;
        int gv = vbase + v;
        sY[j * GP + v] = (gv < N_NODES) ? g_y[(size_t)gv * 128 + j] : 0.f;
    }
    __syncthreads();

    int f0 = (t & 15) * 4;
    int v0 = (t >> 4) * 4;
    unsigned long long accp[4][2];
#pragma unroll
    for (int a = 0; a < 4; a++) { accp[a][0] = 0ull; accp[a][1] = 0ull; }

#pragma unroll 4
    for (int j = 0; j < 128; j++) {
        float4 wv = *reinterpret_cast<float4*>(&sW[j * GP + f0]);
        float4 yv = *reinterpret_cast<float4*>(&sY[j * GP + v0]);
        unsigned long long wp0 = pack2(wv.x, wv.y);
        unsigned long long wp1 = pack2(wv.z, wv.w);
        float yr[4] = {yv.x, yv.y, yv.z, yv.w};
#pragma unroll
        for (int a = 0; a < 4; a++) {
            unsigned long long yb = pack2(yr[a], yr[a]);
            ffma2(accp[a][0], yb, wp0);
            ffma2(accp[a][1], yb, wp1);
        }
    }

    float4 bb = *reinterpret_cast<const float4*>(bvec + f0);
#pragma unroll
    for (int a = 0; a < 4; a++) {
        int v = vbase + v0 + a;
        if (v < N_NODES) {
            float sv = g_s[v];
            float2 c0 = *reinterpret_cast<float2*>(&accp[a][0]);
            float2 c1 = *reinterpret_cast<float2*>(&accp[a][1]);
            float4 o;
            o.x = c0.x + sv * bb.x;
            o.y = c0.y + sv * bb.y;
            o.z = c1.x + sv * bb.z;
            o.w = c1.y + sv * bb.w;
            *reinterpret_cast<float4*>(out + (size_t)v * FDIM + f0) = o;
        }
    }
}

extern "C" void kernel_launch(void* const* d_in, const int* in_sizes, int n_in,
                              void* d_out, int out_size) {
    const float* feat = (const float*)d_in[0];
    const float* loc  = (const float*)d_in[1];
    const float* bnd  = (const float*)d_in[2];
    const float* emb  = (const float*)d_in[3];
    const float* gw   = (const float*)d_in[4];
    const float* aggw = (const float*)d_in[5];
    const float* aggb = (const float*)d_in[6];
    const int* src   = (const int*)d_in[7];
    const int* dst   = (const int*)d_in[8];
    const int* inter = (const int*)d_in[9];
    float* out = (float*)d_out;

    k_prep<<<1024, 256>>>(emb, gw, feat, loc);                      // 1
    k_deg<<<(N_EDGES + 255) / 256, 256>>>(src, dst);                // 2
    k_main<<<(N_EDGES + 255) / 256, 256>>>(bnd, src, dst, inter);   // 3
    size_t smem = 2 * 128 * GP * sizeof(float);
    cudaFuncSetAttribute(k_gemm, cudaFuncAttributeMaxDynamicSharedMemorySize, (int)smem);
    k_gemm<<<(N_NODES + 63) / 64, 256, smem>>>(aggw, aggb, out);    // 4
}

// round 14
// speedup vs baseline: 2.0416x; 1.0003x over previous
#include <cuda_runtime.h>
#include <cuda_fp16.h>

#define N_NODES 50000
#define N_EDGES 500000
#define NUMK 4
#define FDIM 64
#define DDIM 32
#define NBE 64
#define NBND 63
#define GP 68

// Scratch (device globals; zero-initialized at module load).
// g_s/g_cin/g_cout invariant: zero at kernel_launch entry (reset by k_gemm).
__device__ __align__(128) float g_y[(size_t)N_NODES * 128];
__device__ float g_s[N_NODES];
__device__ int g_cin[N_NODES];
__device__ int g_cout[N_NODES];
__device__ __align__(128) __half g_Th[NBE * FDIM];
__device__ __align__(128) __half g_fh[(size_t)N_NODES * FDIM];
__device__ __align__(16) float4 g_loc4[N_NODES];

__device__ __forceinline__ void red_add4(float* p, float x, float y, float z, float w) {
    asm volatile("red.global.add.v4.f32 [%0], {%1,%2,%3,%4};"
                 :: "l"(p), "f"(x), "f"(y), "f"(z), "f"(w));
}
__device__ __forceinline__ void red_add1(float* p, float x) {
    asm volatile("red.global.add.f32 [%0], %1;" :: "l"(p), "f"(x));
}
__device__ __forceinline__ void ffma2(unsigned long long& d,
                                      unsigned long long a, unsigned long long b) {
    asm("fma.rn.f32x2 %0, %1, %2, %0;" : "+l"(d) : "l"(a), "l"(b));
}
__device__ __forceinline__ unsigned long long pack2(float lo, float hi) {
    unsigned long long r;
    asm("mov.b64 %0, {%1, %2};" : "=l"(r) : "f"(lo), "f"(hi));
    return r;
}

// Fused prep + degree histogram. Counters are pre-zeroed (module init or
// previous k_gemm), so atomics can run in the same kernel.
__global__ __launch_bounds__(256) void k_prep(
    const float* __restrict__ emb, const float* __restrict__ gw,
    const float* __restrict__ feat, const float* __restrict__ loc,
    const int* __restrict__ src, const int* __restrict__ dst)
{
    int i = blockIdx.x * blockDim.x + threadIdx.x;
    int stride = gridDim.x * blockDim.x;
    float4 z = make_float4(0.f, 0.f, 0.f, 0.f);
    float4* y4 = reinterpret_cast<float4*>(g_y);
    for (int j = i; j < N_NODES * 32; j += stride) y4[j] = z;
    for (int j = i; j < N_NODES; j += stride) {
        g_loc4[j] = make_float4(loc[j * 3], loc[j * 3 + 1], loc[j * 3 + 2], 0.f);
    }
    const float2* f2 = reinterpret_cast<const float2*>(feat);
    __half2* h2 = reinterpret_cast<__half2*>(g_fh);
    for (int j = i; j < N_NODES * FDIM / 2; j += stride) {
        float2 v = f2[j];
        h2[j] = __floats2half2_rn(v.x, v.y);
    }
    for (int j = i; j < NBE * FDIM; j += stride) {
        int b = j >> 6, f = j & 63;
        float acc = 0.f;
#pragma unroll
        for (int d = 0; d < DDIM; d++) acc += emb[b * DDIM + d] * gw[f * DDIM + d];
        g_Th[j] = __float2half_rn(acc);
    }
    // degree histogram (counters pre-zeroed)
    for (int e = i; e < N_EDGES; e += stride) {
        atomicAdd(&g_cin[dst[e]], 1);
        atomicAdd(&g_cout[src[e]], 1);
    }
}

// Fused dist + feat (unchanged from R13 winner).
__global__ __launch_bounds__(256) void k_main(
    const float* __restrict__ bnd,
    const int* __restrict__ src, const int* __restrict__ dst,
    const int* __restrict__ inter)
{
    __shared__ float sb[64];
    __shared__ __align__(16) __half sT[NBE * FDIM];   // 8 KB
    __shared__ __align__(16) int4 shA[256];
    __shared__ __align__(16) int4 shB[256];

    int t = threadIdx.x;
    if (t < NBND) sb[t] = bnd[t];
    {
        uint2* d = reinterpret_cast<uint2*>(sT);
        const uint2* s = reinterpret_cast<const uint2*>(g_Th);
#pragma unroll
        for (int k = 0; k < 4; k++) d[t + 256 * k] = s[t + 256 * k];
    }
    __syncthreads();

    // ---- phase 1: dist/bucket/sc ----
    int e0 = blockIdx.x * 256 + t;
    if (e0 < N_EDGES) {
        int si = __ldg(&src[e0]);
        int di = __ldg(&dst[e0]);
        float4 sp = __ldg(&g_loc4[si]);

        int others[5];
        others[0] = di;
#pragma unroll
        for (int k = 0; k < NUMK; k++) others[k + 1] = __ldg(&inter[(size_t)e0 * NUMK + k]);

        int pk[5];
#pragma unroll
        for (int s = 0; s < 5; s++) {
            int o = others[s];
            float4 op = __ldg(&g_loc4[o]);
            float dx = sp.x - op.x, dy = sp.y - op.y, dz = sp.z - op.z;
            float dv = sqrtf(dx * dx + dy * dy + dz * dz);
            int pos = 0;
#pragma unroll
            for (int step = 32; step >= 1; step >>= 1)
                if (pos + step <= NBND && sb[pos + step - 1] < dv) pos += step;
            pk[s] = (o << 6) | pos;
        }

        float sc = rsqrtf(fmaxf((float)__ldg(&g_cin[di]), 1.f)) *
                   rsqrtf(fmaxf((float)__ldg(&g_cout[si]), 1.f));
        red_add1(&g_s[di], sc);

        shA[t] = make_int4(si | (di << 16), pk[1], pk[2], pk[3]);
        shB[t] = make_int4(pk[4], pk[0] & 63, __float_as_int(sc), 0);
    }
    __syncthreads();

    // ---- phase 2: feature accumulate ----
    int lane = t & 31;
    int w = t >> 5;
    int hl = lane & 15;
    int half = lane >> 4;
    int j = hl * 4;

#pragma unroll 4
    for (int i = 0; i < 16; i++) {
        int el = w * 32 + i * 2 + half;
        int e = blockIdx.x * 256 + el;
        if (e >= N_EDGES) continue;

        int4 A = shA[el];
        int4 B = shB[el];
        int si = A.x & 0xffff;
        int di = (A.x >> 16) & 0xffff;
        float sc = __int_as_float(B.z);

        uint2 hv = __ldg(reinterpret_cast<const uint2*>(g_fh + (size_t)si * FDIM + j));
        uint2 tv = *reinterpret_cast<const uint2*>(sT + B.y * FDIM + j);
        __half2 p0 = __hmul2(*reinterpret_cast<__half2*>(&hv.x), *reinterpret_cast<__half2*>(&tv.x));
        __half2 p1 = __hmul2(*reinterpret_cast<__half2*>(&hv.y), *reinterpret_cast<__half2*>(&tv.y));
        float2 f0 = __half22float2(p0), f1 = __half22float2(p1);

        float ax = 0.f, ay = 0.f, az = 0.f, aw = 0.f;
        int pv[4] = {A.y, A.z, A.w, B.x};
#pragma unroll
        for (int k = 0; k < NUMK; k++) {
            int id = pv[k] >> 6, bk = pv[k] & 63;
            uint2 h = __ldg(reinterpret_cast<const uint2*>(g_fh + (size_t)id * FDIM + j));
            uint2 tt = *reinterpret_cast<const uint2*>(sT + bk * FDIM + j);
            __half2 q0 = __hmul2(*reinterpret_cast<__half2*>(&h.x), *reinterpret_cast<__half2*>(&tt.x));
            __half2 q1 = __hmul2(*reinterpret_cast<__half2*>(&h.y), *reinterpret_cast<__half2*>(&tt.y));
            float2 g0 = __half22float2(q0), g1 = __half22float2(q1);
            ax += g0.x; ay += g0.y; az += g1.x; aw += g1.y;
        }
        float f4 = sc * 0.25f;

        float* yrow = g_y + (size_t)di * 128;
        red_add4(yrow + j,      sc * f0.x, sc * f0.y, sc * f1.x, sc * f1.y);
        red_add4(yrow + 64 + j, f4 * ax, f4 * ay, f4 * az, f4 * aw);
    }
}

// out[v][f] = sum_j y[v][j] * W[f][j] + s[v] * b[f]
// j chunked in 2x64 -> 34.8 KB smem -> 6 blocks/SM (75% occ).
// Also stashes g_s to smem and resets s/cin/cout for the next replay.
__global__ __launch_bounds__(256) void k_gemm(
    const float* __restrict__ W, const float* __restrict__ bvec,
    float* __restrict__ out)
{
    __shared__ float sW[64 * GP];
    __shared__ float sY[64 * GP];
    __shared__ float sS[64];
    int t = threadIdx.x;
    int vbase = blockIdx.x * 64;
    int gv64 = vbase + t;     // only meaningful for t < 64

    if (t < 64) sS[t] = (gv64 < N_NODES) ? g_s[gv64] : 0.f;
    __syncthreads();          // all g_s reads done; sS visible
    if (t < 64 && gv64 < N_NODES) {
        g_s[gv64] = 0.f; g_cin[gv64] = 0; g_cout[gv64] = 0;   // reset for next call
    }

    int f0 = (t & 15) * 4;
    int v0 = (t >> 4) * 4;
    unsigned long long accp[4][2];
#pragma unroll
    for (int a = 0; a < 4; a++) { accp[a][0] = 0ull; accp[a][1] = 0ull; }

#pragma unroll
    for (int chunk = 0; chunk < 2; chunk++) {
        int jb = chunk * 64;
        // load W chunk: sW[jl*GP + f] = W[f*128 + jb + jl]
        for (int idx = t; idx < 4096; idx += 256) {
            int f = idx >> 6, jl = idx & 63;
            sW[jl * GP + f] = W[f * 128 + jb + jl];
        }
        // load Y chunk: sY[jl*GP + v] = g_y[(vbase+v)*128 + jb + jl]
        for (int idx = t; idx < 4096; idx += 256) {
            int v = idx >> 6, jl = idx & 63;
            int gv = vbase + v;
            sY[jl * GP + v] = (gv < N_NODES) ? g_y[(size_t)gv * 128 + jb + jl] : 0.f;
        }
        __syncthreads();

#pragma unroll 4
        for (int j = 0; j < 64; j++) {
            float4 wv = *reinterpret_cast<float4*>(&sW[j * GP + f0]);
            float4 yv = *reinterpret_cast<float4*>(&sY[j * GP + v0]);
            unsigned long long wp0 = pack2(wv.x, wv.y);
            unsigned long long wp1 = pack2(wv.z, wv.w);
            float yr[4] = {yv.x, yv.y, yv.z, yv.w};
#pragma unroll
            for (int a = 0; a < 4; a++) {
                unsigned long long yb = pack2(yr[a], yr[a]);
                ffma2(accp[a][0], yb, wp0);
                ffma2(accp[a][1], yb, wp1);
            }
        }
        __syncthreads();
    }

    float4 bb = *reinterpret_cast<const float4*>(bvec + f0);
#pragma unroll
    for (int a = 0; a < 4; a++) {
        int v = vbase + v0 + a;
        if (v < N_NODES) {
            float sv = sS[v0 + a];
            float2 c0 = *reinterpret_cast<float2*>(&accp[a][0]);
            float2 c1 = *reinterpret_cast<float2*>(&accp[a][1]);
            float4 o;
            o.x = c0.x + sv * bb.x;
            o.y = c0.y + sv * bb.y;
            o.z = c1.x + sv * bb.z;
            o.w = c1.y + sv * bb.w;
            *reinterpret_cast<float4*>(out + (size_t)v * FDIM + f0) = o;
        }
    }
}

extern "C" void kernel_launch(void* const* d_in, const int* in_sizes, int n_in,
                              void* d_out, int out_size) {
    const float* feat = (const float*)d_in[0];
    const float* loc  = (const float*)d_in[1];
    const float* bnd  = (const float*)d_in[2];
    const float* emb  = (const float*)d_in[3];
    const float* gw   = (const float*)d_in[4];
    const float* aggw = (const float*)d_in[5];
    const float* aggb = (const float*)d_in[6];
    const int* src   = (const int*)d_in[7];
    const int* dst   = (const int*)d_in[8];
    const int* inter = (const int*)d_in[9];
    float* out = (float*)d_out;

    k_prep<<<1024, 256>>>(emb, gw, feat, loc, src, dst);            // 1
    k_main<<<(N_EDGES + 255) / 256, 256>>>(bnd, src, dst, inter);   // 2
    k_gemm<<<(N_NODES + 63) / 64, 256>>>(aggw, aggb, out);          // 3
}

// round 16
// speedup vs baseline: 2.0450x; 1.0017x over previous
#include <cuda_runtime.h>
#include <cuda_fp16.h>

#define N_NODES 50000
#define N_EDGES 500000
#define NUMK 4
#define FDIM 64
#define DDIM 32
#define NBE 64
#define NBND 63
#define GP 68
#define LUTN 2048
#define LUTSCALE 1024.0f

// Scratch (device globals; zero-initialized at module load).
// g_s/g_cin/g_cout invariant: zero at kernel_launch entry (reset by k_gemm).
__device__ __align__(128) float g_y[(size_t)N_NODES * 128];
__device__ float g_s[N_NODES];
__device__ int g_cin[N_NODES];
__device__ int g_cout[N_NODES];
__device__ __align__(128) __half g_Th[NBE * FDIM];
__device__ __align__(128) __half g_fh[(size_t)N_NODES * FDIM];
__device__ __align__(16) float4 g_loc4[N_NODES];
__device__ __align__(16) short g_lut[LUTN];

__device__ __forceinline__ void red_add4(float* p, float x, float y, float z, float w) {
    asm volatile("red.global.add.v4.f32 [%0], {%1,%2,%3,%4};"
                 :: "l"(p), "f"(x), "f"(y), "f"(z), "f"(w));
}
__device__ __forceinline__ void red_add1(float* p, float x) {
    asm volatile("red.global.add.f32 [%0], %1;" :: "l"(p), "f"(x));
}
__device__ __forceinline__ void ffma2(unsigned long long& d,
                                      unsigned long long a, unsigned long long b) {
    asm("fma.rn.f32x2 %0, %1, %2, %0;" : "+l"(d) : "l"(a), "l"(b));
}
__device__ __forceinline__ unsigned long long pack2(float lo, float hi) {
    unsigned long long r;
    asm("mov.b64 %0, {%1, %2};" : "=l"(r) : "f"(lo), "f"(hi));
    return r;
}

// Fused prep + degree histogram + LUT build. Histogram first (longest
// latency stream), streaming stores after.
__global__ __launch_bounds__(256) void k_prep(
    const float* __restrict__ emb, const float* __restrict__ gw,
    const float* __restrict__ feat, const float* __restrict__ loc,
    const int* __restrict__ src, const int* __restrict__ dst,
    const float* __restrict__ bnd)
{
    int i = blockIdx.x * blockDim.x + threadIdx.x;
    int stride = gridDim.x * blockDim.x;

    // degree histogram (counters pre-zeroed by module init / previous k_gemm)
    for (int e = i; e < N_EDGES; e += stride) {
        atomicAdd(&g_cin[dst[e]], 1);
        atomicAdd(&g_cout[src[e]], 1);
    }

    // bucket LUT: lut[q] = count(boundaries < q/LUTSCALE)
    for (int q = i; q < LUTN; q += stride) {
        float v = (float)q * (1.0f / LUTSCALE);
        int pos = 0;
#pragma unroll
        for (int step = 32; step >= 1; step >>= 1)
            if (pos + step <= NBND && __ldg(&bnd[pos + step - 1]) < v) pos += step;
        g_lut[q] = (short)pos;
    }

    float4 z = make_float4(0.f, 0.f, 0.f, 0.f);
    float4* y4 = reinterpret_cast<float4*>(g_y);
    for (int j = i; j < N_NODES * 32; j += stride) y4[j] = z;
    for (int j = i; j < N_NODES; j += stride) {
        g_loc4[j] = make_float4(loc[j * 3], loc[j * 3 + 1], loc[j * 3 + 2], 0.f);
    }
    const float2* f2 = reinterpret_cast<const float2*>(feat);
    __half2* h2 = reinterpret_cast<__half2*>(g_fh);
    for (int j = i; j < N_NODES * FDIM / 2; j += stride) {
        float2 v = f2[j];
        h2[j] = __floats2half2_rn(v.x, v.y);
    }
    for (int j = i; j < NBE * FDIM; j += stride) {
        int b = j >> 6, f = j & 63;
        float acc = 0.f;
#pragma unroll
        for (int d = 0; d < DDIM; d++) acc += emb[b * DDIM + d] * gw[f * DDIM + d];
        g_Th[j] = __float2half_rn(acc);
    }
}

// Fused dist + feat. Phase 1 uses LUT + tiny fixup instead of binary search.
__global__ __launch_bounds__(256) void k_main(
    const float* __restrict__ bnd,
    const int* __restrict__ src, const int* __restrict__ dst,
    const int* __restrict__ inter)
{
    __shared__ float sb[64];
    __shared__ short sLut[LUTN];                      // 4 KB
    __shared__ __align__(16) __half sT[NBE * FDIM];   // 8 KB
    __shared__ __align__(16) int4 shA[256];
    __shared__ __align__(16) int4 shB[256];

    int t = threadIdx.x;
    if (t < NBND) sb[t] = bnd[t];
    else if (t >= 64 && t < 64 + NBE) sb[t - 64] = sb[t - 64]; // no-op keep simple
    {
        uint2* d = reinterpret_cast<uint2*>(sT);
        const uint2* s = reinterpret_cast<const uint2*>(g_Th);
#pragma unroll
        for (int k = 0; k < 4; k++) d[t + 256 * k] = s[t + 256 * k];
        int4* dl = reinterpret_cast<int4*>(sLut);
        const int4* sl = reinterpret_cast<const int4*>(g_lut);
        dl[t] = sl[t];    // 256 * 16B = 4096B = 2048 shorts
    }
    __syncthreads();

    // ---- phase 1: dist/bucket/sc via LUT ----
    int e0 = blockIdx.x * 256 + t;
    if (e0 < N_EDGES) {
        int si = __ldg(&src[e0]);
        int di = __ldg(&dst[e0]);
        float4 sp = __ldg(&g_loc4[si]);

        int others[5];
        others[0] = di;
#pragma unroll
        for (int k = 0; k < NUMK; k++) others[k + 1] = __ldg(&inter[(size_t)e0 * NUMK + k]);

        int pk[5];
#pragma unroll
        for (int s = 0; s < 5; s++) {
            int o = others[s];
            float4 op = __ldg(&g_loc4[o]);
            float dx = sp.x - op.x, dy = sp.y - op.y, dz = sp.z - op.z;
            float dv = sqrtf(dx * dx + dy * dy + dz * dz);
            int q = (int)(dv * LUTSCALE);
            q = min(q, LUTN - 1);
            int pos = sLut[q];
            while (pos < NBND && sb[pos] < dv) pos++;   // avg ~0.03 iters
            pk[s] = (o << 6) | pos;
        }

        float sc = rsqrtf(fmaxf((float)__ldg(&g_cin[di]), 1.f)) *
                   rsqrtf(fmaxf((float)__ldg(&g_cout[si]), 1.f));
        red_add1(&g_s[di], sc);

        shA[t] = make_int4(si | (di << 16), pk[1], pk[2], pk[3]);
        shB[t] = make_int4(pk[4], pk[0] & 63, __float_as_int(sc), 0);
    }
    __syncthreads();

    // ---- phase 2: feature accumulate (divergence-free, 2 edges/warp/iter) ----
    int lane = t & 31;
    int w = t >> 5;
    int hl = lane & 15;
    int half = lane >> 4;
    int j = hl * 4;

#pragma unroll 4
    for (int i = 0; i < 16; i++) {
        int el = w * 32 + i * 2 + half;
        int e = blockIdx.x * 256 + el;
        if (e >= N_EDGES) continue;

        int4 A = shA[el];
        int4 B = shB[el];
        int si = A.x & 0xffff;
        int di = (A.x >> 16) & 0xffff;
        float sc = __int_as_float(B.z);

        uint2 hv = __ldg(reinterpret_cast<const uint2*>(g_fh + (size_t)si * FDIM + j));
        uint2 tv = *reinterpret_cast<const uint2*>(sT + B.y * FDIM + j);
        __half2 p0 = __hmul2(*reinterpret_cast<__half2*>(&hv.x), *reinterpret_cast<__half2*>(&tv.x));
        __half2 p1 = __hmul2(*reinterpret_cast<__half2*>(&hv.y), *reinterpret_cast<__half2*>(&tv.y));
        float2 f0 = __half22float2(p0), f1 = __half22float2(p1);

        float ax = 0.f, ay = 0.f, az = 0.f, aw = 0.f;
        int pv[4] = {A.y, A.z, A.w, B.x};
#pragma unroll
        for (int k = 0; k < NUMK; k++) {
            int id = pv[k] >> 6, bk = pv[k] & 63;
            uint2 h = __ldg(reinterpret_cast<const uint2*>(g_fh + (size_t)id * FDIM + j));
            uint2 tt = *reinterpret_cast<const uint2*>(sT + bk * FDIM + j);
            __half2 q0 = __hmul2(*reinterpret_cast<__half2*>(&h.x), *reinterpret_cast<__half2*>(&tt.x));
            __half2 q1 = __hmul2(*reinterpret_cast<__half2*>(&h.y), *reinterpret_cast<__half2*>(&tt.y));
            float2 g0 = __half22float2(q0), g1 = __half22float2(q1);
            ax += g0.x; ay += g0.y; az += g1.x; aw += g1.y;
        }
        float f4 = sc * 0.25f;

        float* yrow = g_y + (size_t)di * 128;
        red_add4(yrow + j,      sc * f0.x, sc * f0.y, sc * f1.x, sc * f1.y);
        red_add4(yrow + 64 + j, f4 * ax, f4 * ay, f4 * az, f4 * aw);
    }
}

// out[v][f] = sum_j y[v][j] * W[f][j] + s[v] * b[f]
// j chunked 2x64 -> 34.8 KB smem -> 6 blocks/SM. Resets s/cin/cout.
__global__ __launch_bounds__(256) void k_gemm(
    const float* __restrict__ W, const float* __restrict__ bvec,
    float* __restrict__ out)
{
    __shared__ float sW[64 * GP];
    __shared__ float sY[64 * GP];
    __shared__ float sS[64];
    int t = threadIdx.x;
    int vbase = blockIdx.x * 64;
    int gv64 = vbase + t;

    if (t < 64) sS[t] = (gv64 < N_NODES) ? g_s[gv64] : 0.f;
    __syncthreads();
    if (t < 64 && gv64 < N_NODES) {
        g_s[gv64] = 0.f; g_cin[gv64] = 0; g_cout[gv64] = 0;
    }

    int f0 = (t & 15) * 4;
    int v0 = (t >> 4) * 4;
    unsigned long long accp[4][2];
#pragma unroll
    for (int a = 0; a < 4; a++) { accp[a][0] = 0ull; accp[a][1] = 0ull; }

#pragma unroll
    for (int chunk = 0; chunk < 2; chunk++) {
        int jb = chunk * 64;
        for (int idx = t; idx < 4096; idx += 256) {
            int f = idx >> 6, jl = idx & 63;
            sW[jl * GP + f] = W[f * 128 + jb + jl];
        }
        for (int idx = t; idx < 4096; idx += 256) {
            int v = idx >> 6, jl = idx & 63;
            int gv = vbase + v;
            sY[jl * GP + v] = (gv < N_NODES) ? g_y[(size_t)gv * 128 + jb + jl] : 0.f;
        }
        __syncthreads();

#pragma unroll 4
        for (int j = 0; j < 64; j++) {
            float4 wv = *reinterpret_cast<float4*>(&sW[j * GP + f0]);
            float4 yv = *reinterpret_cast<float4*>(&sY[j * GP + v0]);
            unsigned long long wp0 = pack2(wv.x, wv.y);
            unsigned long long wp1 = pack2(wv.z, wv.w);
            float yr[4] = {yv.x, yv.y, yv.z, yv.w};
#pragma unroll
            for (int a = 0; a < 4; a++) {
                unsigned long long yb = pack2(yr[a], yr[a]);
                ffma2(accp[a][0], yb, wp0);
                ffma2(accp[a][1], yb, wp1);
            }
        }
        __syncthreads();
    }

    float4 bb = *reinterpret_cast<const float4*>(bvec + f0);
#pragma unroll
    for (int a = 0; a < 4; a++) {
        int v = vbase + v0 + a;
        if (v < N_NODES) {
            float sv = sS[v0 + a];
            float2 c0 = *reinterpret_cast<float2*>(&accp[a][0]);
            float2 c1 = *reinterpret_cast<float2*>(&accp[a][1]);
            float4 o;
            o.x = c0.x + sv * bb.x;
            o.y = c0.y + sv * bb.y;
            o.z = c1.x + sv * bb.z;
            o.w = c1.y + sv * bb.w;
            *reinterpret_cast<float4*>(out + (size_t)v * FDIM + f0) = o;
        }
    }
}

extern "C" void kernel_launch(void* const* d_in, const int* in_sizes, int n_in,
                              void* d_out, int out_size) {
    const float* feat = (const float*)d_in[0];
    const float* loc  = (const float*)d_in[1];
    const float* bnd  = (const float*)d_in[2];
    const float* emb  = (const float*)d_in[3];
    const float* gw   = (const float*)d_in[4];
    const float* aggw = (const float*)d_in[5];
    const float* aggb = (const float*)d_in[6];
    const int* src   = (const int*)d_in[7];
    const int* dst   = (const int*)d_in[8];
    const int* inter = (const int*)d_in[9];
    float* out = (float*)d_out;

    k_prep<<<1024, 256>>>(emb, gw, feat, loc, src, dst, bnd);       // 1
    k_main<<<(N_EDGES + 255) / 256, 256>>>(bnd, src, dst, inter);   // 2
    k_gemm<<<(N_NODES + 63) / 64, 256>>>(aggw, aggb, out);          // 3
}

// round 17
// speedup vs baseline: 2.3305x; 1.1396x over previous
#include <cuda_runtime.h>
#include <cuda_fp16.h>

#define N_NODES 50000
#define N_EDGES 500000
#define NUMK 4
#define FDIM 64
#define DDIM 32
#define NBE 64
#define NBND 63
#define GP 68
#define LUTN 2048
#define LUTSCALE 1024.0f

// Scratch (device globals; zero-initialized at module load).
// g_s/g_cin/g_cout invariant: zero at kernel_launch entry (reset by k_gemm).
__device__ __align__(128) __half g_yh[(size_t)N_NODES * 128];   // fp16 cat accumulator
__device__ float g_s[N_NODES];
__device__ int g_cin[N_NODES];
__device__ int g_cout[N_NODES];
__device__ __align__(128) __half g_Th[NBE * FDIM];
__device__ __align__(128) __half g_fh[(size_t)N_NODES * FDIM];
__device__ __align__(16) float4 g_loc4[N_NODES];
__device__ __align__(16) short g_lut[LUTN];

__device__ __forceinline__ void red_add1(float* p, float x) {
    asm volatile("red.global.add.f32 [%0], %1;" :: "l"(p), "f"(x));
}
// 4 halves (2x f16x2) in one 8B vector reduction
__device__ __forceinline__ void red_h4(__half* p, unsigned a, unsigned b) {
    asm volatile("red.global.add.noftz.v2.f16x2 [%0], {%1,%2};"
                 :: "l"(p), "r"(a), "r"(b));
}
__device__ __forceinline__ unsigned h2pack(float lo, float hi) {
    __half2 h = __floats2half2_rn(lo, hi);
    return *reinterpret_cast<unsigned*>(&h);
}
__device__ __forceinline__ void ffma2(unsigned long long& d,
                                      unsigned long long a, unsigned long long b) {
    asm("fma.rn.f32x2 %0, %1, %2, %0;" : "+l"(d) : "l"(a), "l"(b));
}
__device__ __forceinline__ unsigned long long pack2(float lo, float hi) {
    unsigned long long r;
    asm("mov.b64 %0, {%1, %2};" : "=l"(r) : "f"(lo), "f"(hi));
    return r;
}

// Fused prep + degree histogram + LUT build.
__global__ __launch_bounds__(256) void k_prep(
    const float* __restrict__ emb, const float* __restrict__ gw,
    const float* __restrict__ feat, const float* __restrict__ loc,
    const int* __restrict__ src, const int* __restrict__ dst,
    const float* __restrict__ bnd)
{
    int i = blockIdx.x * blockDim.x + threadIdx.x;
    int stride = gridDim.x * blockDim.x;

    // degree histogram first (longest latency stream; counters pre-zeroed)
    for (int e = i; e < N_EDGES; e += stride) {
        atomicAdd(&g_cin[dst[e]], 1);
        atomicAdd(&g_cout[src[e]], 1);
    }

    // bucket LUT: lut[q] = count(boundaries < q/LUTSCALE)
    for (int q = i; q < LUTN; q += stride) {
        float v = (float)q * (1.0f / LUTSCALE);
        int pos = 0;
#pragma unroll
        for (int step = 32; step >= 1; step >>= 1)
            if (pos + step <= NBND && __ldg(&bnd[pos + step - 1]) < v) pos += step;
        g_lut[q] = (short)pos;
    }

    // zero fp16 y (12.8 MB)
    uint4 z4 = make_uint4(0u, 0u, 0u, 0u);
    uint4* yh4 = reinterpret_cast<uint4*>(g_yh);
    for (int j = i; j < N_NODES * 16; j += stride) yh4[j] = z4;

    for (int j = i; j < N_NODES; j += stride) {
        g_loc4[j] = make_float4(loc[j * 3], loc[j * 3 + 1], loc[j * 3 + 2], 0.f);
    }
    const float2* f2 = reinterpret_cast<const float2*>(feat);
    __half2* h2 = reinterpret_cast<__half2*>(g_fh);
    for (int j = i; j < N_NODES * FDIM / 2; j += stride) {
        float2 v = f2[j];
        h2[j] = __floats2half2_rn(v.x, v.y);
    }
    for (int j = i; j < NBE * FDIM; j += stride) {
        int b = j >> 6, f = j & 63;
        float acc = 0.f;
#pragma unroll
        for (int d = 0; d < DDIM; d++) acc += emb[b * DDIM + d] * gw[f * DDIM + d];
        g_Th[j] = __float2half_rn(acc);
    }
}

// Fused dist + feat; fp16 vector REDs into g_yh.
__global__ __launch_bounds__(256) void k_main(
    const float* __restrict__ bnd,
    const int* __restrict__ src, const int* __restrict__ dst,
    const int* __restrict__ inter)
{
    __shared__ float sb[64];
    __shared__ short sLut[LUTN];                      // 4 KB
    __shared__ __align__(16) __half sT[NBE * FDIM];   // 8 KB
    __shared__ __align__(16) int4 shA[256];
    __shared__ __align__(16) int4 shB[256];

    int t = threadIdx.x;
    if (t < NBND) sb[t] = bnd[t];
    {
        uint2* d = reinterpret_cast<uint2*>(sT);
        const uint2* s = reinterpret_cast<const uint2*>(g_Th);
#pragma unroll
        for (int k = 0; k < 4; k++) d[t + 256 * k] = s[t + 256 * k];
        int4* dl = reinterpret_cast<int4*>(sLut);
        const int4* sl = reinterpret_cast<const int4*>(g_lut);
        dl[t] = sl[t];
    }
    __syncthreads();

    // ---- phase 1: dist/bucket/sc via LUT ----
    int e0 = blockIdx.x * 256 + t;
    if (e0 < N_EDGES) {
        int si = __ldg(&src[e0]);
        int di = __ldg(&dst[e0]);
        float4 sp = __ldg(&g_loc4[si]);

        int others[5];
        others[0] = di;
#pragma unroll
        for (int k = 0; k < NUMK; k++) others[k + 1] = __ldg(&inter[(size_t)e0 * NUMK + k]);

        int pk[5];
#pragma unroll
        for (int s = 0; s < 5; s++) {
            int o = others[s];
            float4 op = __ldg(&g_loc4[o]);
            float dx = sp.x - op.x, dy = sp.y - op.y, dz = sp.z - op.z;
            float dv = sqrtf(dx * dx + dy * dy + dz * dz);
            int q = (int)(dv * LUTSCALE);
            q = min(q, LUTN - 1);
            int pos = sLut[q];
            while (pos < NBND && sb[pos] < dv) pos++;
            pk[s] = (o << 6) | pos;
        }

        float sc = rsqrtf(fmaxf((float)__ldg(&g_cin[di]), 1.f)) *
                   rsqrtf(fmaxf((float)__ldg(&g_cout[si]), 1.f));
        red_add1(&g_s[di], sc);

        shA[t] = make_int4(si | (di << 16), pk[1], pk[2], pk[3]);
        shB[t] = make_int4(pk[4], pk[0] & 63, __float_as_int(sc), 0);
    }
    __syncthreads();

    // ---- phase 2: feature accumulate (divergence-free, 2 edges/warp/iter) ----
    int lane = t & 31;
    int w = t >> 5;
    int hl = lane & 15;
    int half = lane >> 4;
    int j = hl * 4;

#pragma unroll 4
    for (int i = 0; i < 16; i++) {
        int el = w * 32 + i * 2 + half;
        int e = blockIdx.x * 256 + el;
        if (e >= N_EDGES) continue;

        int4 A = shA[el];
        int4 B = shB[el];
        int si = A.x & 0xffff;
        int di = (A.x >> 16) & 0xffff;
        float sc = __int_as_float(B.z);

        uint2 hv = __ldg(reinterpret_cast<const uint2*>(g_fh + (size_t)si * FDIM + j));
        uint2 tv = *reinterpret_cast<const uint2*>(sT + B.y * FDIM + j);
        __half2 p0 = __hmul2(*reinterpret_cast<__half2*>(&hv.x), *reinterpret_cast<__half2*>(&tv.x));
        __half2 p1 = __hmul2(*reinterpret_cast<__half2*>(&hv.y), *reinterpret_cast<__half2*>(&tv.y));
        float2 f0 = __half22float2(p0), f1 = __half22float2(p1);

        float ax = 0.f, ay = 0.f, az = 0.f, aw = 0.f;
        int pv[4] = {A.y, A.z, A.w, B.x};
#pragma unroll
        for (int k = 0; k < NUMK; k++) {
            int id = pv[k] >> 6, bk = pv[k] & 63;
            uint2 h = __ldg(reinterpret_cast<const uint2*>(g_fh + (size_t)id * FDIM + j));
            uint2 tt = *reinterpret_cast<const uint2*>(sT + bk * FDIM + j);
            __half2 q0 = __hmul2(*reinterpret_cast<__half2*>(&h.x), *reinterpret_cast<__half2*>(&tt.x));
            __half2 q1 = __hmul2(*reinterpret_cast<__half2*>(&h.y), *reinterpret_cast<__half2*>(&tt.y));
            float2 g0 = __half22float2(q0), g1 = __half22float2(q1);
            ax += g0.x; ay += g0.y; az += g1.x; aw += g1.y;
        }
        float f4 = sc * 0.25f;

        __half* yrow = g_yh + (size_t)di * 128;
        red_h4(yrow + j,      h2pack(sc * f0.x, sc * f0.y), h2pack(sc * f1.x, sc * f1.y));
        red_h4(yrow + 64 + j, h2pack(f4 * ax, f4 * ay),     h2pack(f4 * az, f4 * aw));
    }
}

// out[v][f] = sum_j y[v][j] * W[f][j] + s[v] * b[f]
// Reads fp16 y, fp32 FFMA2 core. j chunked 2x64. Resets s/cin/cout.
__global__ __launch_bounds__(256) void k_gemm(
    const float* __restrict__ W, const float* __restrict__ bvec,
    float* __restrict__ out)
{
    __shared__ float sW[64 * GP];
    __shared__ float sY[64 * GP];
    __shared__ float sS[64];
    int t = threadIdx.x;
    int vbase = blockIdx.x * 64;
    int gv64 = vbase + t;

    if (t < 64) sS[t] = (gv64 < N_NODES) ? g_s[gv64] : 0.f;
    __syncthreads();
    if (t < 64 && gv64 < N_NODES) {
        g_s[gv64] = 0.f; g_cin[gv64] = 0; g_cout[gv64] = 0;
    }

    int f0 = (t & 15) * 4;
    int v0 = (t >> 4) * 4;
    unsigned long long accp[4][2];
#pragma unroll
    for (int a = 0; a < 4; a++) { accp[a][0] = 0ull; accp[a][1] = 0ull; }

#pragma unroll
    for (int chunk = 0; chunk < 2; chunk++) {
        int jb = chunk * 64;
        for (int idx = t; idx < 4096; idx += 256) {
            int f = idx >> 6, jl = idx & 63;
            sW[jl * GP + f] = W[f * 128 + jb + jl];
        }
        // y fp16 -> fp32 into smem (half2 loads, 2048 units of 2 halves)
        for (int idx = t; idx < 2048; idx += 256) {
            int v = idx >> 5, jp = (idx & 31) * 2;
            int gv = vbase + v;
            float2 vv = make_float2(0.f, 0.f);
            if (gv < N_NODES) {
                __half2 hh = *reinterpret_cast<const __half2*>(
                    g_yh + (size_t)gv * 128 + jb + jp);
                vv = __half22float2(hh);
            }
            sY[jp * GP + v] = vv.x;
            sY[(jp + 1) * GP + v] = vv.y;
        }
        __syncthreads();

#pragma unroll 4
        for (int j = 0; j < 64; j++) {
            float4 wv = *reinterpret_cast<float4*>(&sW[j * GP + f0]);
            float4 yv = *reinterpret_cast<float4*>(&sY[j * GP + v0]);
            unsigned long long wp0 = pack2(wv.x, wv.y);
            unsigned long long wp1 = pack2(wv.z, wv.w);
            float yr[4] = {yv.x, yv.y, yv.z, yv.w};
#pragma unroll
            for (int a = 0; a < 4; a++) {
                unsigned long long yb = pack2(yr[a], yr[a]);
                ffma2(accp[a][0], yb, wp0);
                ffma2(accp[a][1], yb, wp1);
            }
        }
        __syncthreads();
    }

    float4 bb = *reinterpret_cast<const float4*>(bvec + f0);
#pragma unroll
    for (int a = 0; a < 4; a++) {
        int v = vbase + v0 + a;
        if (v < N_NODES) {
            float sv = sS[v0 + a];
            float2 c0 = *reinterpret_cast<float2*>(&accp[a][0]);
            float2 c1 = *reinterpret_cast<float2*>(&accp[a][1]);
            float4 o;
            o.x = c0.x + sv * bb.x;
            o.y = c0.y + sv * bb.y;
            o.z = c1.x + sv * bb.z;
            o.w = c1.y + sv * bb.w;
            *reinterpret_cast<float4*>(out + (size_t)v * FDIM + f0) = o;
        }
    }
}

extern "C" void kernel_launch(void* const* d_in, const int* in_sizes, int n_in,
                              void* d_out, int out_size) {
    const float* feat = (const float*)d_in[0];
    const float* loc  = (const float*)d_in[1];
    const float* bnd  = (const float*)d_in[2];
    const float* emb  = (const float*)d_in[3];
    const float* gw   = (const float*)d_in[4];
    const float* aggw = (const float*)d_in[5];
    const float* aggb = (const float*)d_in[6];
    const int* src   = (const int*)d_in[7];
    const int* dst   = (const int*)d_in[8];
    const int* inter = (const int*)d_in[9];
    float* out = (float*)d_out;

    k_prep<<<1024, 256>>>(emb, gw, feat, loc, src, dst, bnd);       // 1
    k_main<<<(N_EDGES + 255) / 256, 256>>>(bnd, src, dst, inter);   // 2
    k_gemm<<<(N_NODES + 63) / 64, 256>>>(aggw, aggb, out);          // 3
}